// round 1
// baseline (speedup 1.0000x reference)
#include <cuda_runtime.h>
#include <cstdint>

// lstm_model_8873402433789 — fused LSTM scan + output heads, fp32x2-packed.
// One warp per batch row. Lane j owns hidden unit j (gate cols j, j+32, j+64, j+96).
// U, W in registers as f32x2 pairs; h broadcast via pre-splatted smem;
// x staged through double-buffered smem in 8-step chunks.

#define ULL unsigned long long

static __device__ __forceinline__ ULL pk2(float lo, float hi) {
    ULL r;
    asm("mov.b64 %0, {%1, %2};" : "=l"(r) : "f"(lo), "f"(hi));
    return r;
}
static __device__ __forceinline__ void upk2(ULL v, float& lo, float& hi) {
    asm("mov.b64 {%0, %1}, %2;" : "=f"(lo), "=f"(hi) : "l"(v));
}
static __device__ __forceinline__ ULL fma2(ULL a, ULL b, ULL c) {
    ULL d;
    asm("fma.rn.f32x2 %0, %1, %2, %3;" : "=l"(d) : "l"(a), "l"(b), "l"(c));
    return d;
}
static __device__ __forceinline__ float sigf(float v) {
    return __fdividef(1.0f, 1.0f + __expf(-v));
}

// Shapes (fixed by the reference)
#define BB 8192
#define TT 200
#define FF 16
#define HH 32
#define DD 60
// 25 chunks of 8 timesteps; 8*16 = 128 floats = 32 float4 per chunk (T*F = 3200 = 25*128 exactly)

__global__ void __launch_bounds__(128, 2) lstm_fused_kernel(
    const float* __restrict__ x,   // [B, T, F]
    const float* __restrict__ W,   // [F, 4H]
    const float* __restrict__ U,   // [H, 4H]
    const float* __restrict__ b,   // [4H]
    const float* __restrict__ W1,  // [H, D]
    const float* __restrict__ b1,  // [D]
    const float* __restrict__ W2,  // [H, D]
    const float* __restrict__ b2,  // [D]
    float* __restrict__ out)       // [2, B, D] (long_pred then lat_pred)
{
    __shared__ ULL    hsh[4][2][32];   // per-warp h splat (h,h), double buffered
    __shared__ float4 xsh[4][2][32];   // per-warp x chunk staging, double buffered

    const int w   = threadIdx.x >> 5;
    const int j   = threadIdx.x & 31;
    const int row = blockIdx.x * 4 + w;

    // ---- Load weights into registers (coalesced across lanes, L2-resident) ----
    ULL u01[32], u23[32];
#pragma unroll
    for (int k = 0; k < 32; ++k) {
        const float* Uk = U + k * 128;
        u01[k] = pk2(Uk[j],      Uk[32 + j]);
        u23[k] = pk2(Uk[64 + j], Uk[96 + j]);
    }
    // W paired along f: wq[p] = (W[2p][col_q], W[2p+1][col_q])
    ULL w0[8], w1r[8], w2r[8], w3r[8];
#pragma unroll
    for (int p = 0; p < 8; ++p) {
        const float* Wa = W + (2 * p)     * 128;
        const float* Wb = W + (2 * p + 1) * 128;
        w0[p]  = pk2(Wa[j],      Wb[j]);
        w1r[p] = pk2(Wa[32 + j], Wb[32 + j]);
        w2r[p] = pk2(Wa[64 + j], Wb[64 + j]);
        w3r[p] = pk2(Wa[96 + j], Wb[96 + j]);
    }
    const ULL b01 = pk2(b[j],      b[32 + j]);
    const ULL b23 = pk2(b[64 + j], b[96 + j]);

    const float4* xr4 = (const float4*)(x + (size_t)row * (TT * FF));

    // ---- Init state + first chunk ----
    hsh[w][0][j] = 0ULL;          // splat(h0=0)
    xsh[w][0][j] = xr4[j];        // chunk 0 (steps 0..7)
    __syncwarp();

    float h = 0.0f, c = 0.0f;
    ULL* hb = &hsh[w][0][0];

    for (int chunk = 0; chunk < 25; ++chunk) {
        // Prefetch next chunk (clamped for the last one) — hidden behind 8 steps of compute.
        int nxt = chunk + 1; if (nxt > 24) nxt = 24;
        float4 pf = xr4[nxt * 32 + j];

        const ULL* xb = (const ULL*)&xsh[w][chunk & 1][0];  // 64 float2-pairs

#pragma unroll
        for (int s = 0; s < 8; ++s) {
            // gate accumulators: (i,f) and (c,o) packed pairs, bias-initialized
            ULL a01 = b01, a23 = b23;
            // x-part partials, paired along f (horizontal-reduced at the end)
            ULL x0 = 0, x1 = 0, x2 = 0, x3 = 0;
#pragma unroll
            for (int p = 0; p < 8; ++p) {
                ULL xp = xb[s * 8 + p];          // (x[t][2p], x[t][2p+1]) broadcast LDS.64
                x0 = fma2(xp, w0[p],  x0);
                x1 = fma2(xp, w1r[p], x1);
                x2 = fma2(xp, w2r[p], x2);
                x3 = fma2(xp, w3r[p], x3);
            }
            const ULL* hbr = hb + (s & 1) * 32;  // t ≡ s (mod 2)
#pragma unroll
            for (int k = 0; k < 32; ++k) {
                ULL hk = hbr[k];                 // splat(h_k) broadcast LDS.64
                a01 = fma2(hk, u01[k], a01);
                a23 = fma2(hk, u23[k], a23);
            }
            float gi, gf, gc, go, lo, hi;
            upk2(a01, gi, gf);
            upk2(a23, gc, go);
            upk2(x0, lo, hi); gi += lo + hi;
            upk2(x1, lo, hi); gf += lo + hi;
            upk2(x2, lo, hi); gc += lo + hi;
            upk2(x3, lo, hi); go += lo + hi;

            float ii = sigf(gi);
            float ff = sigf(gf);
            float oo = sigf(go);
            float cc = fmaxf(gc, 0.0f);          // activation=relu on candidate
            c = ff * c + ii * cc;
            h = oo * fmaxf(c, 0.0f);             // relu on cell for hidden

            hb[((s + 1) & 1) * 32 + j] = pk2(h, h);
            __syncwarp();
        }
        // Commit prefetched chunk to the other buffer, then make it visible.
        xsh[w][(chunk + 1) & 1][j] = pf;
        __syncwarp();
    }

    // ---- Output heads: long = h@W1+b1, lat = h@W2+b2 ----
    // Final h_200 splats live in buffer 0 (200 is even).
    const float* hf = (const float*)&hsh[w][0][0];   // hf[2k] = h_k
    float* outL = out;
    float* outA = out + (size_t)BB * DD;
#pragma unroll
    for (int rep = 0; rep < 2; ++rep) {
        int d = j + rep * 32;
        if (d < DD) {
            float aL = b1[d], aA = b2[d];
#pragma unroll
            for (int k = 0; k < 32; ++k) {
                float hk = hf[2 * k];
                aL = fmaf(hk, W1[k * DD + d], aL);
                aA = fmaf(hk, W2[k * DD + d], aA);
            }
            outL[(size_t)row * DD + d] = aL;
            outA[(size_t)row * DD + d] = aA;
        }
    }
}

extern "C" void kernel_launch(void* const* d_in, const int* in_sizes, int n_in,
                              void* d_out, int out_size) {
    const float* x  = (const float*)d_in[0];
    const float* W  = (const float*)d_in[1];
    const float* U  = (const float*)d_in[2];
    const float* b  = (const float*)d_in[3];
    const float* W1 = (const float*)d_in[4];
    const float* b1 = (const float*)d_in[5];
    const float* W2 = (const float*)d_in[6];
    const float* b2 = (const float*)d_in[7];
    float* out = (float*)d_out;

    // 8192 rows, 1 warp/row, 4 warps/block -> 2048 blocks
    lstm_fused_kernel<<<2048, 128>>>(x, W, U, b, W1, b1, W2, b2, out);
}

// round 2
// speedup vs baseline: 1.0265x; 1.0265x over previous
#include <cuda_runtime.h>
#include <cstdint>

// lstm_model_8873402433789 R2 — fused LSTM, fp32x2-packed, gate-major x,
// 2 independent rows per warp (tail-latency hiding), LDS.128 splat reads.

#define ULL unsigned long long

static __device__ __forceinline__ ULL pk2(float lo, float hi) {
    ULL r;
    asm("mov.b64 %0, {%1, %2};" : "=l"(r) : "f"(lo), "f"(hi));
    return r;
}
static __device__ __forceinline__ void upk2(ULL v, float& lo, float& hi) {
    asm("mov.b64 {%0, %1}, %2;" : "=f"(lo), "=f"(hi) : "l"(v));
}
static __device__ __forceinline__ ULL fma2(ULL a, ULL b, ULL c) {
    ULL d;
    asm("fma.rn.f32x2 %0, %1, %2, %3;" : "=l"(d) : "l"(a), "l"(b), "l"(c));
    return d;
}
static __device__ __forceinline__ float sigf(float v) {
    return __fdividef(1.0f, 1.0f + __expf(-v));
}

#define BB 8192
#define TT 200
#define FF 16
#define HH 32
#define DD 60
// 25 chunks x 8 steps; 8*16 floats = 32 float4 per chunk per row.

__global__ void __launch_bounds__(128, 2) lstm_fused2_kernel(
    const float* __restrict__ x,   // [B, T, F]
    const float* __restrict__ W,   // [F, 4H]
    const float* __restrict__ U,   // [H, 4H]
    const float* __restrict__ b,   // [4H]
    const float* __restrict__ W1,  // [H, D]
    const float* __restrict__ b1,  // [D]
    const float* __restrict__ W2,  // [H, D]
    const float* __restrict__ b2,  // [D]
    float* __restrict__ out)       // [2, B, D]
{
    // [warp][row][buf][...] splat buffers, 16B-aligned for LDS.128
    __shared__ __align__(16) ULL hs[4][2][2][32];    // h splats (h,h)
    __shared__ __align__(16) ULL xs[4][2][2][128];   // x splats, [step*16+f]

    const int w  = threadIdx.x >> 5;
    const int j  = threadIdx.x & 31;
    const int row0 = blockIdx.x * 8 + w * 2;   // this warp's two rows

    // ---- Weights into registers (shared across both rows) ----
    ULL u01[32], u23[32];
#pragma unroll
    for (int k = 0; k < 32; ++k) {
        const float* Uk = U + k * 128;
        u01[k] = pk2(Uk[j],      Uk[32 + j]);
        u23[k] = pk2(Uk[64 + j], Uk[96 + j]);
    }
    // Gate-major W: w01[f] = (W[f][j], W[f][32+j]) so splat(x_f) FMAs straight
    // into the (i,f) / (c,o) gate accumulators.
    ULL w01[16], w23[16];
#pragma unroll
    for (int f = 0; f < 16; ++f) {
        const float* Wf = W + f * 128;
        w01[f] = pk2(Wf[j],      Wf[32 + j]);
        w23[f] = pk2(Wf[64 + j], Wf[96 + j]);
    }
    const ULL b01 = pk2(b[j],      b[32 + j]);
    const ULL b23 = pk2(b[64 + j], b[96 + j]);

    const float4* xA = (const float4*)(x + (size_t)row0 * (TT * FF));
    const float4* xB = (const float4*)(x + (size_t)(row0 + 1) * (TT * FF));

    // ---- Init h splats + stage chunk 0 as splats ----
    hs[w][0][0][j] = 0ULL;
    hs[w][1][0][j] = 0ULL;
    {
        float4 va = xA[j], vb = xB[j];
        int si = (j >> 2) * 16 + (j & 3) * 4;
        ULL* d0 = &xs[w][0][0][si];
        d0[0] = pk2(va.x, va.x); d0[1] = pk2(va.y, va.y);
        d0[2] = pk2(va.z, va.z); d0[3] = pk2(va.w, va.w);
        ULL* d1 = &xs[w][1][0][si];
        d1[0] = pk2(vb.x, vb.x); d1[1] = pk2(vb.y, vb.y);
        d1[2] = pk2(vb.z, vb.z); d1[3] = pk2(vb.w, vb.w);
    }
    __syncwarp();

    float c0 = 0.0f, c1 = 0.0f;

    for (int chunk = 0; chunk < 25; ++chunk) {
        const int cb = chunk & 1;
        // Prefetch next chunk straight into the spare buffer (clamped last).
        {
            int nxt = chunk + 1; if (nxt > 24) nxt = 24;
            float4 pa = xA[nxt * 32 + j];
            float4 pb = xB[nxt * 32 + j];
            int si = (j >> 2) * 16 + (j & 3) * 4;
            ULL* d0 = &xs[w][0][cb ^ 1][si];
            d0[0] = pk2(pa.x, pa.x); d0[1] = pk2(pa.y, pa.y);
            d0[2] = pk2(pa.z, pa.z); d0[3] = pk2(pa.w, pa.w);
            ULL* d1 = &xs[w][1][cb ^ 1][si];
            d1[0] = pk2(pb.x, pb.x); d1[1] = pk2(pb.y, pb.y);
            d1[2] = pk2(pb.z, pb.z); d1[3] = pk2(pb.w, pb.w);
        }

#pragma unroll 2
        for (int s = 0; s < 8; ++s) {
            const int par = s & 1;     // global t = chunk*8+s, chunk*8 even
            ULL a01 = b01, a23 = b23;  // row 0 gate accumulators (i,f)/(c,o)
            ULL g01 = b01, g23 = b23;  // row 1

            // x-part (h-independent; schedulable into prior step's tail)
            const ulonglong2* xq0 = (const ulonglong2*)&xs[w][0][cb][s * 16];
            const ulonglong2* xq1 = (const ulonglong2*)&xs[w][1][cb][s * 16];
#pragma unroll
            for (int p = 0; p < 8; ++p) {
                ulonglong2 v0 = xq0[p];
                a01 = fma2(v0.x, w01[2 * p],     a01);
                a23 = fma2(v0.x, w23[2 * p],     a23);
                a01 = fma2(v0.y, w01[2 * p + 1], a01);
                a23 = fma2(v0.y, w23[2 * p + 1], a23);
                ulonglong2 v1 = xq1[p];
                g01 = fma2(v1.x, w01[2 * p],     g01);
                g23 = fma2(v1.x, w23[2 * p],     g23);
                g01 = fma2(v1.y, w01[2 * p + 1], g01);
                g23 = fma2(v1.y, w23[2 * p + 1], g23);
            }

            // h-part (recurrent)
            const ulonglong2* hq0 = (const ulonglong2*)&hs[w][0][par][0];
            const ulonglong2* hq1 = (const ulonglong2*)&hs[w][1][par][0];
#pragma unroll
            for (int k = 0; k < 16; ++k) {
                ulonglong2 h0 = hq0[k];
                a01 = fma2(h0.x, u01[2 * k],     a01);
                a23 = fma2(h0.x, u23[2 * k],     a23);
                a01 = fma2(h0.y, u01[2 * k + 1], a01);
                a23 = fma2(h0.y, u23[2 * k + 1], a23);
                ulonglong2 h1 = hq1[k];
                g01 = fma2(h1.x, u01[2 * k],     g01);
                g23 = fma2(h1.x, u23[2 * k],     g23);
                g01 = fma2(h1.y, u01[2 * k + 1], g01);
                g23 = fma2(h1.y, u23[2 * k + 1], g23);
            }

            // Tails (rows independent -> interleave)
            {
                float gi, gf, gc, go;
                upk2(a01, gi, gf); upk2(a23, gc, go);
                float ii = sigf(gi), ff = sigf(gf), oo = sigf(go);
                c0 = ff * c0 + ii * fmaxf(gc, 0.0f);
                float h0 = oo * fmaxf(c0, 0.0f);
                hs[w][0][par ^ 1][j] = pk2(h0, h0);
            }
            {
                float gi, gf, gc, go;
                upk2(g01, gi, gf); upk2(g23, gc, go);
                float ii = sigf(gi), ff = sigf(gf), oo = sigf(go);
                c1 = ff * c1 + ii * fmaxf(gc, 0.0f);
                float h1 = oo * fmaxf(c1, 0.0f);
                hs[w][1][par ^ 1][j] = pk2(h1, h1);
            }
            __syncwarp();
        }
        __syncwarp();   // prefetch stores visible before next chunk reads
    }

    // ---- Output heads for both rows (final h in buffer 0: t=200 even) ----
    float* outL = out;
    float* outA = out + (size_t)BB * DD;
#pragma unroll
    for (int r = 0; r < 2; ++r) {
        const float* hf = (const float*)&hs[w][r][0][0];  // hf[2k] = h_k
        const size_t row = row0 + r;
#pragma unroll
        for (int rep = 0; rep < 2; ++rep) {
            int d = j + rep * 32;
            if (d < DD) {
                float aL = b1[d], aA = b2[d];
#pragma unroll
                for (int k = 0; k < 32; ++k) {
                    float hk = hf[2 * k];
                    aL = fmaf(hk, W1[k * DD + d], aL);
                    aA = fmaf(hk, W2[k * DD + d], aA);
                }
                outL[row * DD + d] = aL;
                outA[row * DD + d] = aA;
            }
        }
    }
}

extern "C" void kernel_launch(void* const* d_in, const int* in_sizes, int n_in,
                              void* d_out, int out_size) {
    const float* x  = (const float*)d_in[0];
    const float* W  = (const float*)d_in[1];
    const float* U  = (const float*)d_in[2];
    const float* b  = (const float*)d_in[3];
    const float* W1 = (const float*)d_in[4];
    const float* b1 = (const float*)d_in[5];
    const float* W2 = (const float*)d_in[6];
    const float* b2 = (const float*)d_in[7];
    float* out = (float*)d_out;

    // 8192 rows, 2 rows/warp, 4 warps/block -> 1024 blocks
    lstm_fused2_kernel<<<1024, 128>>>(x, W, U, b, W1, b1, W2, b2, out);
}